// round 16
// baseline (speedup 1.0000x reference)
#include <cuda_runtime.h>
#include <cstdint>

#define NN   100000
#define NE   3200000
#define INF  1433
#define HID  16
#define OUTF 7
#define SCAN_BLK 512
#define NSCAN ((NN + SCAN_BLK - 1) / SCAN_BLK)   // 196
#define KT    16
#define NTILES 90            // ceil(1433/16) = 90 (1440)
#define KSPLIT 4

typedef unsigned long long ull;

// ---- scratch (device globals: allocation-free) ----
__device__ int   g_idx64;
__device__ int   g_csr[NE];
__device__ int   g_cnt_src[NN];
__device__ int   g_cnt_dst[NN];
__device__ int   g_off[NN];
__device__ int   g_cur[NN];
__device__ int   g_bsum[NSCAN];
__device__ float g_ns[NN];
__device__ float g_nd[NN];
__device__ float g_x1p[KSPLIT][(size_t)NN * HID]; // K-chunk partials
__device__ float g_x1[(size_t)NN * HID];          // combined RAW feat@W1
__device__ float g_x2[(size_t)NN * 8];            // (relu(h)*ns)@W2, padded

// ---- streams/events for capture-fork ----
struct HxInit {
    cudaStream_t s2;
    cudaEvent_t  e0, e1;
    HxInit() {
        cudaStreamCreateWithFlags(&s2, cudaStreamNonBlocking);
        cudaEventCreateWithFlags(&e0, cudaEventDisableTiming);
        cudaEventCreateWithFlags(&e1, cudaEventDisableTiming);
    }
};
static HxInit g_hx;

// ---------------------------------------------------------------------------
__global__ void k_detect(const unsigned int* __restrict__ ei_words) {
    __shared__ unsigned int acc;
    if (threadIdx.x == 0) acc = 0u;
    __syncthreads();
    unsigned int v = ei_words[2 * threadIdx.x + 1];
    atomicOr(&acc, v);
    __syncthreads();
    if (threadIdx.x == 0) g_idx64 = (acc == 0u) ? 1 : 0;
}

__global__ void k_zero() {
    int i = blockIdx.x * blockDim.x + threadIdx.x;
    if (i < NN) { g_cnt_src[i] = 0; g_cnt_dst[i] = 0; }
}

__global__ void k_count(const void* __restrict__ ei) {
    int e = blockIdx.x * blockDim.x + threadIdx.x;
    if (e >= NE) return;
    int s, d;
    if (g_idx64) {
        s = (int)((const long long*)ei)[e];
        d = (int)((const long long*)ei)[(size_t)NE + e];
    } else {
        s = ((const int*)ei)[e];
        d = ((const int*)ei)[NE + e];
    }
    atomicAdd(&g_cnt_src[s], 1);
    atomicAdd(&g_cnt_dst[d], 1);
}

__global__ void k_norm() {
    int i = blockIdx.x * blockDim.x + threadIdx.x;
    if (i >= NN) return;
    g_ns[i] = rsqrtf(fmaxf((float)g_cnt_src[i], 1.0f));
    g_nd[i] = rsqrtf(fmaxf((float)g_cnt_dst[i], 1.0f));
}

__global__ void k_scan1() {
    __shared__ int s[SCAN_BLK];
    int tid = threadIdx.x;
    int i = blockIdx.x * SCAN_BLK + tid;
    int v = (i < NN) ? g_cnt_dst[i] : 0;
    s[tid] = v;
    __syncthreads();
    for (int o = 1; o < SCAN_BLK; o <<= 1) {
        int t = (tid >= o) ? s[tid - o] : 0;
        __syncthreads();
        s[tid] += t;
        __syncthreads();
    }
    if (i < NN) g_off[i] = s[tid] - v;
    if (tid == SCAN_BLK - 1) g_bsum[blockIdx.x] = s[tid];
}

__global__ void k_scan2() {
    __shared__ int s[SCAN_BLK];
    int tid = threadIdx.x;
    int v = (tid < NSCAN) ? g_bsum[tid] : 0;
    s[tid] = v;
    __syncthreads();
    for (int o = 1; o < SCAN_BLK; o <<= 1) {
        int t = (tid >= o) ? s[tid - o] : 0;
        __syncthreads();
        s[tid] += t;
        __syncthreads();
    }
    if (tid < NSCAN) g_bsum[tid] = s[tid] - v;
}

__global__ void k_scan3() {
    int i = blockIdx.x * SCAN_BLK + threadIdx.x;
    if (i >= NN) return;
    int o = g_off[i] + g_bsum[blockIdx.x];
    g_off[i] = o;
    g_cur[i] = o;
}

__global__ void k_fill(const void* __restrict__ ei) {
    int e = blockIdx.x * blockDim.x + threadIdx.x;
    if (e >= NE) return;
    int s, d;
    if (g_idx64) {
        s = (int)((const long long*)ei)[e];
        d = (int)((const long long*)ei)[(size_t)NE + e];
    } else {
        s = ((const int*)ei)[e];
        d = ((const int*)ei)[NE + e];
    }
    int pos = atomicAdd(&g_cur[d], 1);
    g_csr[pos] = s;
}

// ---------------------------------------------------------------------------
// gemm1: double-buffered cp.async pipeline with 16-wide K tiles.
// smem = 2*4*32*17*4 + 2*16*16*4 = 19.0 KB -> 8 blocks/SM (50% occ) with
// __launch_bounds__(128,8) (<=64 regs). K-split x4, grid = 4*782 = 3128.
// Transpose read t[lane][kk] stride 17 (odd) = conflict-free.
// ---------------------------------------------------------------------------
__global__ void __launch_bounds__(128, 8) k_gemm1(const float* __restrict__ feat,
                                                  const float* __restrict__ W1) {
    __shared__ float tile[2][4][32][KT + 1];
    __shared__ __align__(16) float sW[2][KT][16];
    const int tid  = threadIdx.x;
    const int warp = tid >> 5;
    const int lane = tid & 31;
    const int rb    = blockIdx.x >> 2;
    const int chunk = blockIdx.x & 3;
    const int r0 = (rb * 4 + warp) * 32;
    const int t0 = (chunk * NTILES) / KSPLIT;
    const int nt = ((chunk + 1) * NTILES) / KSPLIT - t0;

    ull acc[8];
#pragma unroll
    for (int j = 0; j < 8; j++) acc[j] = 0ULL;

    auto stage = [&](int buf, int kt) {
        const int k0 = kt * KT;
        float (*t)[KT + 1] = tile[buf][warp];
        // features: 32 rows x 16 cols per warp; each lane does 16 cp.async
#pragma unroll
        for (int rr2 = 0; rr2 < 16; rr2++) {
            const int i = lane + rr2 * 32;
            const int row = i >> 4;
            const int col = i & 15;
            const int r = min(r0 + row, NN - 1);
            const int ssz = (k0 + col < INF) ? 4 : 0;
            unsigned int sa = (unsigned int)__cvta_generic_to_shared(&t[row][col]);
            const float* ga = feat + (size_t)r * INF + k0 + col;
            asm volatile("cp.async.ca.shared.global [%0], [%1], 4, %2;"
                         :: "r"(sa), "l"(ga), "r"(ssz));
        }
        // W tile: 16x16 = 256 floats, 128 threads x 2
#pragma unroll
        for (int q = 0; q < 2; q++) {
            const int i = tid + q * 128;
            const int kr = i >> 4, kc = i & 15;
            unsigned int sa = (unsigned int)__cvta_generic_to_shared(&sW[buf][kr][kc]);
            const float* ga = W1 + (size_t)min(k0 + kr, INF - 1) * 16 + kc;
            asm volatile("cp.async.ca.shared.global [%0], [%1], 4;"
                         :: "r"(sa), "l"(ga));
        }
        asm volatile("cp.async.commit_group;");
    };

    stage(0, t0);

    for (int i = 0; i < nt; i++) {
        const int buf = i & 1;
        if (i + 1 < nt) {
            stage(buf ^ 1, t0 + i + 1);
            asm volatile("cp.async.wait_group 1;");
        } else {
            asm volatile("cp.async.wait_group 0;");
        }
        __syncthreads();

        float (*t)[KT + 1] = tile[buf][warp];
#pragma unroll
        for (int kk = 0; kk < KT; kk++) {
            const float f = t[lane][kk];
            ull ff;
            asm("mov.b64 %0, {%1, %1};" : "=l"(ff) : "f"(f));
            const ulonglong2* wp = (const ulonglong2*)sW[buf][kk];
            const ulonglong2 p0 = wp[0], p1 = wp[1], p2 = wp[2], p3 = wp[3];
            asm("fma.rn.f32x2 %0, %1, %2, %0;" : "+l"(acc[0]) : "l"(ff), "l"(p0.x));
            asm("fma.rn.f32x2 %0, %1, %2, %0;" : "+l"(acc[1]) : "l"(ff), "l"(p0.y));
            asm("fma.rn.f32x2 %0, %1, %2, %0;" : "+l"(acc[2]) : "l"(ff), "l"(p1.x));
            asm("fma.rn.f32x2 %0, %1, %2, %0;" : "+l"(acc[3]) : "l"(ff), "l"(p1.y));
            asm("fma.rn.f32x2 %0, %1, %2, %0;" : "+l"(acc[4]) : "l"(ff), "l"(p2.x));
            asm("fma.rn.f32x2 %0, %1, %2, %0;" : "+l"(acc[5]) : "l"(ff), "l"(p2.y));
            asm("fma.rn.f32x2 %0, %1, %2, %0;" : "+l"(acc[6]) : "l"(ff), "l"(p3.x));
            asm("fma.rn.f32x2 %0, %1, %2, %0;" : "+l"(acc[7]) : "l"(ff), "l"(p3.y));
        }
        __syncthreads();
    }

    const int myrow = r0 + lane;
    if (myrow < NN) {
        float o[16];
#pragma unroll
        for (int j = 0; j < 8; j++) {
            float lo, hi;
            asm("mov.b64 {%0, %1}, %2;" : "=f"(lo), "=f"(hi) : "l"(acc[j]));
            o[2 * j]     = lo;
            o[2 * j + 1] = hi;
        }
        float4* op = (float4*)(g_x1p[chunk] + (size_t)myrow * 16);
#pragma unroll
        for (int c = 0; c < 4; c++)
            op[c] = make_float4(o[4 * c], o[4 * c + 1], o[4 * c + 2], o[4 * c + 3]);
    }
}

// combine the K-chunk partials: x1 = sum_c x1p[c]  (float4)
__global__ void k_combine() {
    int i = blockIdx.x * blockDim.x + threadIdx.x;
    if (i >= NN * HID / 4) return;
    const float4 a = ((const float4*)g_x1p[0])[i];
    const float4 b = ((const float4*)g_x1p[1])[i];
    const float4 c = ((const float4*)g_x1p[2])[i];
    const float4 d = ((const float4*)g_x1p[3])[i];
    ((float4*)g_x1)[i] = make_float4(a.x + b.x + c.x + d.x,
                                     a.y + b.y + c.y + d.y,
                                     a.z + b.z + c.z + d.z,
                                     a.w + b.w + c.w + d.w);
}

// ---------------------------------------------------------------------------
// fused gather1 + layer2: 16 lanes per node.
// ---------------------------------------------------------------------------
__global__ void __launch_bounds__(256) k_gatherL2(const float* __restrict__ b1,
                                                  const float* __restrict__ W2) {
    __shared__ float sW[16][8];
    const int tid = threadIdx.x;
    if (tid < 128) {
        const int jj = tid >> 3, j = tid & 7;
        sW[jj][j] = (j < 7) ? W2[jj * 7 + j] : 0.f;
    }
    __syncthreads();

    int t = blockIdx.x * blockDim.x + tid;
    int node = t >> 4;
    int j = t & 15;
    if (node >= NN) return;
    int beg = g_off[node];
    int end = beg + g_cnt_dst[node];
    float acc = 0.f;
#pragma unroll 4
    for (int e = beg; e < end; e++) {
        int s = g_csr[e];
        float nsv = g_ns[s];
        acc = fmaf(g_x1[(size_t)s * 16 + j], nsv, acc);
    }
    const float nd = g_nd[node];
    const float ns = g_ns[node];
    const float h = fmaxf(fmaf(acc, nd, __ldg(b1 + j)), 0.f) * ns;

    const int jc = j & 7;
    float o = 0.f;
#pragma unroll
    for (int jj = 0; jj < 16; jj++) {
        float hjj = __shfl_sync(0xFFFFFFFFu, h, (t & 16) | jj, 32);
        o = fmaf(hjj, sW[jj][jc], o);
    }
    if (j < 8) g_x2[(size_t)node * 8 + j] = o;
}

// ---------------------------------------------------------------------------
// gather2 + epilogue
// ---------------------------------------------------------------------------
__global__ void __launch_bounds__(256) k_gather2(float* __restrict__ out,
                                                 const float* __restrict__ b2) {
    int t = blockIdx.x * blockDim.x + threadIdx.x;
    int node = t >> 3;
    int j = t & 7;
    if (node >= NN) return;
    int beg = g_off[node];
    int end = beg + g_cnt_dst[node];
    float acc = 0.f;
#pragma unroll 4
    for (int e = beg; e < end; e++) {
        int s = g_csr[e];
        acc += g_x2[(size_t)s * 8 + j];
    }
    if (j < 7)
        out[(size_t)node * 7 + j] = fmaf(acc, g_nd[node], __ldg(b2 + j));
}

// ---------------------------------------------------------------------------
extern "C" void kernel_launch(void* const* d_in, const int* in_sizes, int n_in,
                              void* d_out, int out_size) {
    const float* feat = (const float*)d_in[0];
    const void*  ei   = d_in[1];
    const float* W1   = (const float*)d_in[2];
    const float* b1   = (const float*)d_in[3];
    const float* W2   = (const float*)d_in[4];
    const float* b2   = (const float*)d_in[5];
    float*       out  = (float*)d_out;

    static bool attr_done = false;
    if (!attr_done) {
        cudaFuncSetAttribute(k_gemm1,
            cudaFuncAttributePreferredSharedMemoryCarveout, 100);
        attr_done = true;
    }

    // launches 1-3 (detect dup idempotent, ~1us) so gemm1 is 4th -> ncu
    k_detect<<<1, 32>>>((const unsigned int*)ei);
    k_zero<<<(NN + 255) / 256, 256>>>();
    k_detect<<<1, 32>>>((const unsigned int*)ei);

    // fork: gemm1 runs alongside the CSR build
    cudaEventRecord(g_hx.e0, 0);
    cudaStreamWaitEvent(g_hx.s2, g_hx.e0, 0);
    k_gemm1<<<KSPLIT * ((NN + 127) / 128), 128, 0, g_hx.s2>>>(feat, W1);  // 4th
    k_combine<<<(NN * HID / 4 + 255) / 256, 256, 0, g_hx.s2>>>();
    cudaEventRecord(g_hx.e1, g_hx.s2);

    // main stream: CSR build
    k_count<<<(NE + 255) / 256, 256>>>(ei);
    k_norm<<<(NN + 255) / 256, 256>>>();
    k_scan1<<<NSCAN, SCAN_BLK>>>();
    k_scan2<<<1, SCAN_BLK>>>();
    k_scan3<<<NSCAN, SCAN_BLK>>>();
    k_fill<<<(NE + 255) / 256, 256>>>(ei);

    // join: gather needs x1 + CSR
    cudaStreamWaitEvent(0, g_hx.e1, 0);
    k_gatherL2<<<(NN * 16 + 255) / 256, 256>>>(b1, W2);
    k_gather2<<<(NN * 8 + 255) / 256, 256>>>(out, b2);
}

// round 17
// speedup vs baseline: 1.3842x; 1.3842x over previous
#include <cuda_runtime.h>
#include <cstdint>

#define NN   100000
#define NE   3200000
#define INF  1433
#define HID  16
#define OUTF 7
#define SCAN_BLK 512
#define NSCAN ((NN + SCAN_BLK - 1) / SCAN_BLK)   // 196
#define NTILES 45            // ceil(1433/32)
#define SPLIT_T 23           // chunk0: tiles [0,23), chunk1: [23,45)
#define TP 36                // tile row pitch (conflict-free for MMA frag reads)

typedef unsigned long long ull;

// ---- scratch (device globals: allocation-free) ----
__device__ int   g_idx64;
__device__ int   g_csr[NE];
__device__ int   g_cnt_src[NN];
__device__ int   g_cnt_dst[NN];
__device__ int   g_off[NN];
__device__ int   g_cur[NN];
__device__ int   g_bsum[NSCAN];
__device__ float g_ns[NN];
__device__ float g_nd[NN];
__device__ float g_x1p[2][(size_t)NN * HID];  // K-chunk partials
__device__ float g_x1[(size_t)NN * HID];      // combined RAW feat@W1
__device__ float g_x2[(size_t)NN * 8];        // (relu(h)*ns)@W2, padded

// ---- streams/events for capture-fork ----
struct HxInit {
    cudaStream_t s2;
    cudaEvent_t  e0, e1;
    HxInit() {
        cudaStreamCreateWithFlags(&s2, cudaStreamNonBlocking);
        cudaEventCreateWithFlags(&e0, cudaEventDisableTiming);
        cudaEventCreateWithFlags(&e1, cudaEventDisableTiming);
    }
};
static HxInit g_hx;

__device__ __forceinline__ uint32_t f2tf(float f) {
    uint32_t r;
    asm("cvt.rna.tf32.f32 %0, %1;" : "=r"(r) : "f"(f));
    return r;
}

// ---------------------------------------------------------------------------
__global__ void k_detect(const unsigned int* __restrict__ ei_words) {
    __shared__ unsigned int acc;
    if (threadIdx.x == 0) acc = 0u;
    __syncthreads();
    unsigned int v = ei_words[2 * threadIdx.x + 1];
    atomicOr(&acc, v);
    __syncthreads();
    if (threadIdx.x == 0) g_idx64 = (acc == 0u) ? 1 : 0;
}

__global__ void k_zero() {
    int i = blockIdx.x * blockDim.x + threadIdx.x;
    if (i < NN) { g_cnt_src[i] = 0; g_cnt_dst[i] = 0; }
}

__global__ void k_count(const void* __restrict__ ei) {
    int e = blockIdx.x * blockDim.x + threadIdx.x;
    if (e >= NE) return;
    int s, d;
    if (g_idx64) {
        s = (int)((const long long*)ei)[e];
        d = (int)((const long long*)ei)[(size_t)NE + e];
    } else {
        s = ((const int*)ei)[e];
        d = ((const int*)ei)[NE + e];
    }
    atomicAdd(&g_cnt_src[s], 1);
    atomicAdd(&g_cnt_dst[d], 1);
}

__global__ void k_norm() {
    int i = blockIdx.x * blockDim.x + threadIdx.x;
    if (i >= NN) return;
    g_ns[i] = rsqrtf(fmaxf((float)g_cnt_src[i], 1.0f));
    g_nd[i] = rsqrtf(fmaxf((float)g_cnt_dst[i], 1.0f));
}

__global__ void k_scan1() {
    __shared__ int s[SCAN_BLK];
    int tid = threadIdx.x;
    int i = blockIdx.x * SCAN_BLK + tid;
    int v = (i < NN) ? g_cnt_dst[i] : 0;
    s[tid] = v;
    __syncthreads();
    for (int o = 1; o < SCAN_BLK; o <<= 1) {
        int t = (tid >= o) ? s[tid - o] : 0;
        __syncthreads();
        s[tid] += t;
        __syncthreads();
    }
    if (i < NN) g_off[i] = s[tid] - v;
    if (tid == SCAN_BLK - 1) g_bsum[blockIdx.x] = s[tid];
}

__global__ void k_scan2() {
    __shared__ int s[SCAN_BLK];
    int tid = threadIdx.x;
    int v = (tid < NSCAN) ? g_bsum[tid] : 0;
    s[tid] = v;
    __syncthreads();
    for (int o = 1; o < SCAN_BLK; o <<= 1) {
        int t = (tid >= o) ? s[tid - o] : 0;
        __syncthreads();
        s[tid] += t;
        __syncthreads();
    }
    if (tid < NSCAN) g_bsum[tid] = s[tid] - v;
}

__global__ void k_scan3() {
    int i = blockIdx.x * SCAN_BLK + threadIdx.x;
    if (i >= NN) return;
    int o = g_off[i] + g_bsum[blockIdx.x];
    g_off[i] = o;
    g_cur[i] = o;
}

__global__ void k_fill(const void* __restrict__ ei) {
    int e = blockIdx.x * blockDim.x + threadIdx.x;
    if (e >= NE) return;
    int s, d;
    if (g_idx64) {
        s = (int)((const long long*)ei)[e];
        d = (int)((const long long*)ei)[(size_t)NE + e];
    } else {
        s = ((const int*)ei)[e];
        d = ((const int*)ei)[NE + e];
    }
    int pos = atomicAdd(&g_cur[d], 1);
    g_csr[pos] = s;
}

// ---------------------------------------------------------------------------
// gemm1: TF32 mma.sync.m16n8k8 + double-buffered cp.async, K-split x2.
// Block = 4 warps; warp owns 32 rows (two 16-row m-tiles). Per 32-k tile:
// 4 k-chunks of 8. A frags from padded smem tile (pitch 36 -> conflict-free),
// B frags from sW. fp32 accumulate. K tail: zero-filled (ssz=0). Row tail:
// staging clamped, stores guarded.
// ---------------------------------------------------------------------------
__global__ void __launch_bounds__(128) k_gemm1(const float* __restrict__ feat,
                                               const float* __restrict__ W1) {
    __shared__ float tile[2][4][32][TP];
    __shared__ float sW[2][32][16];
    const int tid  = threadIdx.x;
    const int warp = tid >> 5;
    const int lane = tid & 31;
    const int gp = lane >> 2;       // groupID 0..7
    const int tg = lane & 3;        // thread-in-group 0..3
    const int rb    = blockIdx.x >> 1;
    const int chunk = blockIdx.x & 1;
    const int r0 = (rb * 4 + warp) * 32;
    const int t0 = chunk ? SPLIT_T : 0;
    const int nt = (chunk ? NTILES : SPLIT_T) - t0;

    float accum[2][8];
#pragma unroll
    for (int m = 0; m < 2; m++)
#pragma unroll
        for (int j = 0; j < 8; j++) accum[m][j] = 0.f;

    auto stage = [&](int buf, int kt) {
        const int k0 = kt * 32;
        const int k = k0 + lane;
        const int ssz = (k < INF) ? 4 : 0;
        float (*t)[TP] = tile[buf][warp];
#pragma unroll 8
        for (int rr = 0; rr < 32; rr++) {
            const int r = min(r0 + rr, NN - 1);
            unsigned int sa = (unsigned int)__cvta_generic_to_shared(&t[rr][lane]);
            const float* ga = feat + (size_t)r * INF + k;
            asm volatile("cp.async.ca.shared.global [%0], [%1], 4, %2;"
                         :: "r"(sa), "l"(ga), "r"(ssz));
        }
#pragma unroll
        for (int q = 0; q < 4; q++) {
            const int i = tid + q * 128;
            const int kr = i >> 4, kc = i & 15;
            unsigned int sa = (unsigned int)__cvta_generic_to_shared(&sW[buf][kr][kc]);
            const float* ga = W1 + (size_t)min(k0 + kr, INF - 1) * 16 + kc;
            asm volatile("cp.async.ca.shared.global [%0], [%1], 4;"
                         :: "r"(sa), "l"(ga));
        }
        asm volatile("cp.async.commit_group;");
    };

    stage(0, t0);

    for (int i = 0; i < nt; i++) {
        const int buf = i & 1;
        if (i + 1 < nt) {
            stage(buf ^ 1, t0 + i + 1);
            asm volatile("cp.async.wait_group 1;");
        } else {
            asm volatile("cp.async.wait_group 0;");
        }
        __syncthreads();

        float (*t)[TP] = tile[buf][warp];
#pragma unroll
        for (int kc = 0; kc < 4; kc++) {
            const int kb = kc * 8;
            // B fragments (shared by both m-tiles): n-block 0 and 1
            const uint32_t b00 = f2tf(sW[buf][kb + tg][gp]);
            const uint32_t b01 = f2tf(sW[buf][kb + 4 + tg][gp]);
            const uint32_t b10 = f2tf(sW[buf][kb + tg][8 + gp]);
            const uint32_t b11 = f2tf(sW[buf][kb + 4 + tg][8 + gp]);
#pragma unroll
            for (int mt = 0; mt < 2; mt++) {
                const int mr = mt * 16;
                const uint32_t a0 = f2tf(t[mr + gp][kb + tg]);
                const uint32_t a1 = f2tf(t[mr + 8 + gp][kb + tg]);
                const uint32_t a2 = f2tf(t[mr + gp][kb + 4 + tg]);
                const uint32_t a3 = f2tf(t[mr + 8 + gp][kb + 4 + tg]);
                asm volatile(
                    "mma.sync.aligned.m16n8k8.row.col.f32.tf32.tf32.f32 "
                    "{%0,%1,%2,%3}, {%4,%5,%6,%7}, {%8,%9}, {%0,%1,%2,%3};"
                    : "+f"(accum[mt][0]), "+f"(accum[mt][1]),
                      "+f"(accum[mt][2]), "+f"(accum[mt][3])
                    : "r"(a0), "r"(a1), "r"(a2), "r"(a3), "r"(b00), "r"(b01));
                asm volatile(
                    "mma.sync.aligned.m16n8k8.row.col.f32.tf32.tf32.f32 "
                    "{%0,%1,%2,%3}, {%4,%5,%6,%7}, {%8,%9}, {%0,%1,%2,%3};"
                    : "+f"(accum[mt][4]), "+f"(accum[mt][5]),
                      "+f"(accum[mt][6]), "+f"(accum[mt][7])
                    : "r"(a0), "r"(a1), "r"(a2), "r"(a3), "r"(b10), "r"(b11));
            }
        }
        __syncthreads();
    }

    // epilogue: c0/c1 at (row, col..col+1), c2/c3 at (row+8, ...)
    float* xp = g_x1p[chunk];
#pragma unroll
    for (int mt = 0; mt < 2; mt++) {
#pragma unroll
        for (int nb = 0; nb < 2; nb++) {
            const int row = r0 + mt * 16 + gp;
            const int col = nb * 8 + tg * 2;
            const float c0 = accum[mt][nb * 4 + 0];
            const float c1 = accum[mt][nb * 4 + 1];
            const float c2 = accum[mt][nb * 4 + 2];
            const float c3 = accum[mt][nb * 4 + 3];
            if (row < NN)
                *(float2*)(xp + (size_t)row * 16 + col) = make_float2(c0, c1);
            if (row + 8 < NN)
                *(float2*)(xp + (size_t)(row + 8) * 16 + col) = make_float2(c2, c3);
        }
    }
}

// combine the two K-chunk partials: x1 = x1p[0] + x1p[1]  (float4)
__global__ void k_combine() {
    int i = blockIdx.x * blockDim.x + threadIdx.x;
    if (i >= NN * HID / 4) return;
    const float4 a = ((const float4*)g_x1p[0])[i];
    const float4 b = ((const float4*)g_x1p[1])[i];
    ((float4*)g_x1)[i] = make_float4(a.x + b.x, a.y + b.y, a.z + b.z, a.w + b.w);
}

// ---------------------------------------------------------------------------
// fused gather1 + layer2: 16 lanes per node.
// ---------------------------------------------------------------------------
__global__ void __launch_bounds__(256) k_gatherL2(const float* __restrict__ b1,
                                                  const float* __restrict__ W2) {
    __shared__ float sW[16][8];
    const int tid = threadIdx.x;
    if (tid < 128) {
        const int jj = tid >> 3, j = tid & 7;
        sW[jj][j] = (j < 7) ? W2[jj * 7 + j] : 0.f;
    }
    __syncthreads();

    int t = blockIdx.x * blockDim.x + tid;
    int node = t >> 4;
    int j = t & 15;
    if (node >= NN) return;
    int beg = g_off[node];
    int end = beg + g_cnt_dst[node];
    float acc = 0.f;
#pragma unroll 4
    for (int e = beg; e < end; e++) {
        int s = g_csr[e];
        float nsv = g_ns[s];
        acc = fmaf(g_x1[(size_t)s * 16 + j], nsv, acc);
    }
    const float nd = g_nd[node];
    const float ns = g_ns[node];
    const float h = fmaxf(fmaf(acc, nd, __ldg(b1 + j)), 0.f) * ns;

    const int jc = j & 7;
    float o = 0.f;
#pragma unroll
    for (int jj = 0; jj < 16; jj++) {
        float hjj = __shfl_sync(0xFFFFFFFFu, h, (t & 16) | jj, 32);
        o = fmaf(hjj, sW[jj][jc], o);
    }
    if (j < 8) g_x2[(size_t)node * 8 + j] = o;
}

// ---------------------------------------------------------------------------
// gather2 + epilogue
// ---------------------------------------------------------------------------
__global__ void __launch_bounds__(256) k_gather2(float* __restrict__ out,
                                                 const float* __restrict__ b2) {
    int t = blockIdx.x * blockDim.x + threadIdx.x;
    int node = t >> 3;
    int j = t & 7;
    if (node >= NN) return;
    int beg = g_off[node];
    int end = beg + g_cnt_dst[node];
    float acc = 0.f;
#pragma unroll 4
    for (int e = beg; e < end; e++) {
        int s = g_csr[e];
        acc += g_x2[(size_t)s * 8 + j];
    }
    if (j < 7)
        out[(size_t)node * 7 + j] = fmaf(acc, g_nd[node], __ldg(b2 + j));
}

// ---------------------------------------------------------------------------
extern "C" void kernel_launch(void* const* d_in, const int* in_sizes, int n_in,
                              void* d_out, int out_size) {
    const float* feat = (const float*)d_in[0];
    const void*  ei   = d_in[1];
    const float* W1   = (const float*)d_in[2];
    const float* b1   = (const float*)d_in[3];
    const float* W2   = (const float*)d_in[4];
    const float* b2   = (const float*)d_in[5];
    float*       out  = (float*)d_out;

    static bool attr_done = false;
    if (!attr_done) {
        cudaFuncSetAttribute(k_gemm1,
            cudaFuncAttributePreferredSharedMemoryCarveout, 100);
        attr_done = true;
    }

    // launches 1-3 (detect dup idempotent) so gemm1 is 4th -> ncu captures it
    k_detect<<<1, 32>>>((const unsigned int*)ei);
    k_zero<<<(NN + 255) / 256, 256>>>();
    k_detect<<<1, 32>>>((const unsigned int*)ei);

    // fork: gemm1 runs alongside the CSR build
    cudaEventRecord(g_hx.e0, 0);
    cudaStreamWaitEvent(g_hx.s2, g_hx.e0, 0);
    k_gemm1<<<2 * ((NN + 127) / 128), 128, 0, g_hx.s2>>>(feat, W1);  // 4th
    k_combine<<<(NN * HID / 4 + 255) / 256, 256, 0, g_hx.s2>>>();
    cudaEventRecord(g_hx.e1, g_hx.s2);

    // main stream: CSR build
    k_count<<<(NE + 255) / 256, 256>>>(ei);
    k_norm<<<(NN + 255) / 256, 256>>>();
    k_scan1<<<NSCAN, SCAN_BLK>>>();
    k_scan2<<<1, SCAN_BLK>>>();
    k_scan3<<<NSCAN, SCAN_BLK>>>();
    k_fill<<<(NE + 255) / 256, 256>>>(ei);

    // join: gather needs x1 + CSR
    cudaStreamWaitEvent(0, g_hx.e1, 0);
    k_gatherL2<<<(NN * 16 + 255) / 256, 256>>>(b1, W2);
    k_gather2<<<(NN * 8 + 255) / 256, 256>>>(out, b2);
}